// round 2
// baseline (speedup 1.0000x reference)
#include <cuda_runtime.h>
#include <cuda_bf16.h>
#include <math_constants.h>

#define NROW 32768      // B*H*W = 32*32*32
#define CDIM 256
#define NE   1024
#define BM   64
#define BN   64
#define BK   32
#define NTILE (NE/BN)        // 16
#define NCHUNK (CDIM/BK)     // 8
#define GTOT (NTILE*NCHUNK)  // 128
#define NBLK (NROW/BM)       // 512

// scratch (allocation-free rule: __device__ globals)
__device__ float  g_zkm[(size_t)CDIM * NROW];   // z transposed: [c][n], n=b*1024+hw
__device__ float  g_embT[(size_t)CDIM * NE];    // embeddings transposed: [k][j]
__device__ float  g_sz[NROW];
__device__ float  g_se[NE];
__device__ double g_partial[NBLK];

// ---------------- z transpose: (b,c,hw) -> zkm[c][b*1024+hw] ----------------
__global__ void zt_kernel(const float4* __restrict__ z4) {
    int i4 = blockIdx.x * 256 + threadIdx.x;   // 2,097,152 float4 exactly
    int hw4 = i4 & 255;
    int c   = (i4 >> 8) & 255;
    int b   = i4 >> 16;
    ((float4*)g_zkm)[((c << 5) + b) * 256 + hw4] = z4[i4];
}

// ---------------- emb transpose: emb[j][k] -> embT[k][j] ----------------
__global__ void et_kernel(const float* __restrict__ e) {
    int i = blockIdx.x * 256 + threadIdx.x;    // 262144
    int j = i & 1023, k = i >> 10;
    g_embT[i] = e[j * 256 + k];
}

// ---------------- per-code squared norms ----------------
__global__ void se_kernel(const float* __restrict__ e) {
    int j = blockIdx.x;
    float4 v = *(const float4*)&e[j * 256 + threadIdx.x * 4];
    float s = __fadd_rn(__fadd_rn(__fmul_rn(v.x,v.x), __fmul_rn(v.y,v.y)),
                        __fadd_rn(__fmul_rn(v.z,v.z), __fmul_rn(v.w,v.w)));
    for (int off = 16; off; off >>= 1) s += __shfl_down_sync(0xffffffffu, s, off);
    __shared__ float r2[2];
    if ((threadIdx.x & 31) == 0) r2[threadIdx.x >> 5] = s;
    __syncthreads();
    if (threadIdx.x == 0) g_se[j] = __fadd_rn(r2[0], r2[1]);
}

// ---------------- per-row squared norms (from zkm, coalesced) ----------------
__global__ void sz_kernel() {
    int n = blockIdx.x * 32 + threadIdx.x;
    float s = 0.f;
    for (int c = threadIdx.y; c < CDIM; c += 8) {
        float v = g_zkm[(size_t)c * NROW + n];
        s = __fadd_rn(s, __fmul_rn(v, v));
    }
    __shared__ float red[8][32];
    red[threadIdx.y][threadIdx.x] = s;
    __syncthreads();
    if (threadIdx.y == 0) {
        float t = red[0][threadIdx.x];
        #pragma unroll
        for (int y = 1; y < 8; y++) t = __fadd_rn(t, red[y][threadIdx.x]);
        g_sz[n] = t;
    }
}

// ---------------- fused distance + argmin + per-block loss partial ----------------
__global__ void __launch_bounds__(256, 2) vq_main_kernel(float* __restrict__ out) {
    extern __shared__ float sm[];
    float (*As)[BM] = (float(*)[BM])sm;                 // [256][64]  64KB
    float (*Bs)[BN] = (float(*)[BN])(sm + CDIM * BM);   // [32][64]   8KB

    const int tid  = threadIdx.x;
    const int tx   = tid & 15;
    const int ty   = tid >> 4;
    const int row0 = blockIdx.x * BM;

    // load full A tile (k-major) : As[k][r] = zkm[k][row0+r]
    #pragma unroll
    for (int q = 0; q < 16; ++q) {
        int f = tid + q * 256;          // 0..4095
        int k = f >> 4, j4 = f & 15;
        float4 v = *(const float4*)&g_zkm[(size_t)k * NROW + row0 + j4 * 4];
        *(float4*)&As[k][j4 * 4] = v;
    }

    float szr[4];
    #pragma unroll
    for (int i = 0; i < 4; i++) szr[i] = g_sz[row0 + ty * 4 + i];

    float bd[4]; int bi[4];
    #pragma unroll
    for (int i = 0; i < 4; i++) { bd[i] = CUDART_INF_F; bi[i] = 0; }

    // prefetch B chunk 0 into registers
    const int k0 = tid >> 4,          j0 = tid & 15;
    const int k1 = (tid + 256) >> 4,  j1 = (tid + 256) & 15;
    float4 p0 = *(const float4*)&g_embT[(size_t)k0 * NE + j0 * 4];
    float4 p1 = *(const float4*)&g_embT[(size_t)k1 * NE + j1 * 4];

    float acc[4][4];

    for (int g = 0; g < GTOT; ++g) {
        __syncthreads();                       // prior chunk's readers done
        *(float4*)&Bs[k0][j0 * 4] = p0;
        *(float4*)&Bs[k1][j1 * 4] = p1;
        if (g + 1 < GTOT) {
            int gn = g + 1, tile = gn >> 3, kc = gn & 7;
            p0 = *(const float4*)&g_embT[(size_t)(kc * BK + k0) * NE + tile * BN + j0 * 4];
            p1 = *(const float4*)&g_embT[(size_t)(kc * BK + k1) * NE + tile * BN + j1 * 4];
        }
        __syncthreads();                       // Bs (and on g==0, As) visible

        const int kc = g & 7, tile = g >> 3;
        if (kc == 0) {
            #pragma unroll
            for (int i = 0; i < 4; i++)
                #pragma unroll
                for (int j = 0; j < 4; j++) acc[i][j] = 0.f;
        }
        const int kbase = kc * BK;
        #pragma unroll
        for (int k = 0; k < BK; ++k) {
            float4 a = *(const float4*)&As[kbase + k][ty * 4];
            float4 b = *(const float4*)&Bs[k][tx * 4];
            acc[0][0] = fmaf(a.x, b.x, acc[0][0]);
            acc[0][1] = fmaf(a.x, b.y, acc[0][1]);
            acc[0][2] = fmaf(a.x, b.z, acc[0][2]);
            acc[0][3] = fmaf(a.x, b.w, acc[0][3]);
            acc[1][0] = fmaf(a.y, b.x, acc[1][0]);
            acc[1][1] = fmaf(a.y, b.y, acc[1][1]);
            acc[1][2] = fmaf(a.y, b.z, acc[1][2]);
            acc[1][3] = fmaf(a.y, b.w, acc[1][3]);
            acc[2][0] = fmaf(a.z, b.x, acc[2][0]);
            acc[2][1] = fmaf(a.z, b.y, acc[2][1]);
            acc[2][2] = fmaf(a.z, b.z, acc[2][2]);
            acc[2][3] = fmaf(a.z, b.w, acc[2][3]);
            acc[3][0] = fmaf(a.w, b.x, acc[3][0]);
            acc[3][1] = fmaf(a.w, b.y, acc[3][1]);
            acc[3][2] = fmaf(a.w, b.z, acc[3][2]);
            acc[3][3] = fmaf(a.w, b.w, acc[3][3]);
        }
        if (kc == 7) {
            // d = fl( fl(sz+se) - 2*dot )  -- matches jax (A+B) - 2*matmul rounding
            #pragma unroll
            for (int j = 0; j < 4; j++) {
                int code = tile * BN + tx * 4 + j;
                float sej = g_se[code];
                #pragma unroll
                for (int i = 0; i < 4; i++) {
                    float t = __fadd_rn(szr[i], sej);
                    float d = fmaf(-2.0f, acc[i][j], t);
                    if (d < bd[i] || (d == bd[i] && code < bi[i])) { bd[i] = d; bi[i] = code; }
                }
            }
        }
    }

    // cross-thread argmin reduction (16 tx groups per row), lowest-index tie-break
    __syncthreads();
    float* red_d = (float*)Bs;            // 1024 floats
    int*   red_i = (int*)(red_d + 1024);  // 1024 ints  (== Bs 8KB exactly)
    #pragma unroll
    for (int i = 0; i < 4; i++) {
        int r = ty * 4 + i;
        red_d[r * 16 + tx] = bd[i];
        red_i[r * 16 + tx] = bi[i];
    }
    __syncthreads();
    double* rowsum = (double*)As;         // reuse A tile space
    if (tid < BM) {
        float best = red_d[tid * 16]; int bidx = red_i[tid * 16];
        #pragma unroll
        for (int t = 1; t < 16; t++) {
            float d = red_d[tid * 16 + t]; int c = red_i[tid * 16 + t];
            if (d < best || (d == best && c < bidx)) { best = d; bidx = c; }
        }
        out[row0 + tid] = (float)bidx;
        rowsum[tid] = (double)best;       // d_min == sum_c (z_q - z)^2 for this row
    }
    __syncthreads();
    if (tid < 32) {
        double s = rowsum[tid] + rowsum[tid + 32];
        for (int off = 16; off; off >>= 1)
            s += __shfl_down_sync(0xffffffffu, s, off);
        if (tid == 0) g_partial[blockIdx.x] = s;
    }
}

// ---------------- deterministic loss finalize ----------------
__global__ void loss_kernel(float* __restrict__ out, int out_size) {
    __shared__ double s[256];
    s[threadIdx.x] = g_partial[threadIdx.x] + g_partial[threadIdx.x + 256];
    __syncthreads();
    for (int off = 128; off; off >>= 1) {
        if (threadIdx.x < off) s[threadIdx.x] += s[threadIdx.x + off];
        __syncthreads();
    }
    if (threadIdx.x == 0 && out_size > NROW) {
        float m = (float)(s[0] / (double)((size_t)NROW * CDIM));
        out[NROW] = m + 0.25f * m;   // mean((sg(zq)-z)^2) + BETA*mean((zq-sg(z))^2)
    }
}

extern "C" void kernel_launch(void* const* d_in, const int* in_sizes, int n_in,
                              void* d_out, int out_size) {
    const float* z   = (const float*)d_in[0];   // (32,256,32,32) fp32
    const float* emb = (const float*)d_in[1];   // (1024,256)     fp32
    float* out = (float*)d_out;

    zt_kernel<<<8192, 256>>>((const float4*)z);
    et_kernel<<<1024, 256>>>(emb);
    se_kernel<<<1024, 64>>>(emb);
    sz_kernel<<<1024, dim3(32, 8)>>>();

    const int smem_bytes = (CDIM * BM + BK * BN) * (int)sizeof(float);  // 73728
    cudaFuncSetAttribute(vq_main_kernel, cudaFuncAttributeMaxDynamicSharedMemorySize, smem_bytes);
    vq_main_kernel<<<NBLK, 256, smem_bytes>>>(out);

    loss_kernel<<<1, 256>>>(out, out_size);
}

// round 4
// speedup vs baseline: 1.8045x; 1.8045x over previous
#include <cuda_runtime.h>
#include <cuda_bf16.h>
#include <cuda_fp16.h>
#include <math_constants.h>

#define NROW 32768
#define CDIM 256
#define NE   1024
#define MARGIN 8e-3f

// ---- static device scratch (allocation-free rule) ----
__device__ float          g_zrm[(size_t)NROW * CDIM];   // z row-major [n][c] fp32
__device__ __nv_bfloat16  g_zbf[(size_t)NROW * CDIM];   // bf16(z) [n][c]
__device__ __nv_bfloat16  g_ebf[(size_t)NE * CDIM];     // bf16(emb) [j][k]
__device__ float          g_sz[NROW];
__device__ float          g_se[NE];
__device__ __half         g_t[(size_t)NROW * NE];       // approx scores [row][code]
__device__ double         g_partial[4096];

// ================= PTX helpers (baseline sm_80 ISA only) =================
__device__ __forceinline__ unsigned smem_u32(const void* p) {
    unsigned a;
    asm("{ .reg .u64 t; cvta.to.shared.u64 t, %1; cvt.u32.u64 %0, t; }" : "=r"(a) : "l"(p));
    return a;
}
__device__ __forceinline__ void cp16(unsigned dst, const void* src) {
    asm volatile("cp.async.cg.shared.global [%0], [%1], 16;" :: "r"(dst), "l"(src));
}
#define CP_COMMIT() asm volatile("cp.async.commit_group;" ::: "memory")
#define CP_WAIT(n)  asm volatile("cp.async.wait_group %0;" :: "n"(n) : "memory")

__device__ __forceinline__ void ldsm4(unsigned& r0, unsigned& r1, unsigned& r2, unsigned& r3,
                                      unsigned addr) {
    asm volatile("ldmatrix.sync.aligned.m8n8.x4.shared.b16 {%0,%1,%2,%3}, [%4];"
        : "=r"(r0), "=r"(r1), "=r"(r2), "=r"(r3) : "r"(addr));
}
__device__ __forceinline__ void mma16816(float* c, const unsigned* a, unsigned b0, unsigned b1) {
    asm volatile("mma.sync.aligned.m16n8k16.row.col.f32.bf16.bf16.f32 "
        "{%0,%1,%2,%3}, {%4,%5,%6,%7}, {%8,%9}, {%0,%1,%2,%3};"
        : "+f"(c[0]), "+f"(c[1]), "+f"(c[2]), "+f"(c[3])
        : "r"(a[0]), "r"(a[1]), "r"(a[2]), "r"(a[3]), "r"(b0), "r"(b1));
}

// ================= prep kernels =================
// z (b,c,hw) -> zrm[n][c] fp32 + zbf[n][c] bf16, n = b*1024+hw
__global__ void zprep_kernel(const float* __restrict__ z) {
    __shared__ float tile[32][33];
    int tx = threadIdx.x, ty = threadIdx.y;
    int hw0 = blockIdx.x * 32, c0 = blockIdx.y * 32, b = blockIdx.z;
    #pragma unroll
    for (int yy = 0; yy < 4; yy++) {
        int cl = ty + yy * 8;
        tile[cl][tx] = z[((size_t)(b * 256 + c0 + cl)) * 1024 + hw0 + tx];
    }
    __syncthreads();
    #pragma unroll
    for (int yy = 0; yy < 4; yy++) {
        int rl = ty + yy * 8;
        size_t n = (size_t)b * 1024 + hw0 + rl;
        float v = tile[tx][rl];
        g_zrm[n * 256 + c0 + tx] = v;
        g_zbf[n * 256 + c0 + tx] = __float2bfloat16(v);
    }
}

__global__ void eprep_kernel(const float* __restrict__ e) {
    int i = blockIdx.x * 256 + threadIdx.x;   // 262144
    g_ebf[i] = __float2bfloat16(e[i]);
}

// per-code norms (verbatim R1 rounding — known-passing)
__global__ void se_kernel(const float* __restrict__ e) {
    int j = blockIdx.x;
    float4 v = *(const float4*)&e[j * 256 + threadIdx.x * 4];
    float s = __fadd_rn(__fadd_rn(__fmul_rn(v.x,v.x), __fmul_rn(v.y,v.y)),
                        __fadd_rn(__fmul_rn(v.z,v.z), __fmul_rn(v.w,v.w)));
    for (int off = 16; off; off >>= 1) s += __shfl_down_sync(0xffffffffu, s, off);
    __shared__ float r2[2];
    if ((threadIdx.x & 31) == 0) r2[threadIdx.x >> 5] = s;
    __syncthreads();
    if (threadIdx.x == 0) g_se[j] = __fadd_rn(r2[0], r2[1]);
}

// per-row norms — replicates R1 sz_kernel's exact summation order
__global__ void sz2_kernel() {
    int w = threadIdx.x >> 5, lane = threadIdx.x & 31;
    int row = blockIdx.x * 32 + w * 4 + (lane >> 3);
    int y = lane & 7;
    const float* zp = g_zrm + (size_t)row * CDIM;
    float p = 0.f;
    #pragma unroll 8
    for (int i = 0; i < 32; i++) {
        float v = zp[y + 8 * i];
        p = __fadd_rn(p, __fmul_rn(v, v));
    }
    int base = lane & 24;
    float t = __shfl_sync(0xffffffffu, p, base);
    #pragma unroll
    for (int yy = 1; yy < 8; yy++)
        t = __fadd_rn(t, __shfl_sync(0xffffffffu, p, base + yy));
    if (y == 0) g_sz[row] = t;
}

// ================= HMMA approximate scoring =================
// smem: se 4KB | A 64KB (128x256 bf16, xor-swizzled 512B rows) | B 2x64KB
#define SE_OFF 0
#define A_OFF  4096
#define B_OFF  (4096 + 65536)
#define SMEM_T (4096 + 65536 + 2 * 65536)   // 200704

__global__ void __launch_bounds__(512, 1) gemm_kernel() {
    extern __shared__ char sm[];
    unsigned smb = smem_u32(sm);
    const int tid = threadIdx.x, l = tid & 31, w = tid >> 5;
    const int wm = w & 3, wn = w >> 2;           // 4x4 warp grid, 32x32 tiles
    const int row0 = blockIdx.x * 128;
    float* se_sm = (float*)(sm + SE_OFF);

    if (tid < 256) ((float4*)se_sm)[tid] = ((const float4*)g_se)[tid];

    // ---- group 0: A tile + B chunk 0 ----
    const char* zsrc = (const char*)g_zbf + (size_t)row0 * 512;
    #pragma unroll
    for (int i = 0; i < 8; i++) {
        int f = tid + i * 512, r = f >> 5, kb16 = f & 31;
        cp16(smb + A_OFF + r * 512 + ((kb16 * 16) ^ ((r & 7) << 4)),
             zsrc + (size_t)r * 512 + kb16 * 16);
    }
    const char* esrc = (const char*)g_ebf;
    #pragma unroll
    for (int i = 0; i < 8; i++) {
        int f = tid + i * 512, r = f >> 5, kb16 = f & 31;
        cp16(smb + B_OFF + r * 512 + ((kb16 * 16) ^ ((r & 7) << 4)),
             esrc + (size_t)r * 512 + kb16 * 16);
    }
    CP_COMMIT();

    // per-lane ldmatrix address components (swizzle folded into xor constant)
    const unsigned c16 = ((l >> 4) & 1) * 16;
    unsigned aBase[2], xA[2];
    #pragma unroll
    for (int mf = 0; mf < 2; mf++) {
        int r = wm * 32 + mf * 16 + (l & 15);
        aBase[mf] = smb + A_OFF + r * 512;
        xA[mf] = c16 ^ ((r & 7) << 4);
    }
    unsigned bRow[2], xB[2];
    #pragma unroll
    for (int nfp = 0; nfp < 2; nfp++) {
        int r = wn * 32 + nfp * 16 + ((l >> 3) & 1) * 8 + (l & 7);
        bRow[nfp] = r * 512;
        xB[nfp] = c16 ^ ((r & 7) << 4);
    }

    for (int t = 0; t < 8; t++) {
        if (t < 7) {   // prefetch next B chunk into other buffer
            const char* src = esrc + (size_t)(t + 1) * 128 * 512;
            unsigned dstb = smb + B_OFF + ((t + 1) & 1) * 65536;
            #pragma unroll
            for (int i = 0; i < 8; i++) {
                int f = tid + i * 512, r = f >> 5, kb16 = f & 31;
                cp16(dstb + r * 512 + ((kb16 * 16) ^ ((r & 7) << 4)),
                     src + (size_t)r * 512 + kb16 * 16);
            }
            CP_COMMIT();
            CP_WAIT(1);
        } else {
            CP_WAIT(0);
        }
        __syncthreads();

        float acc[2][4][4];
        #pragma unroll
        for (int mf = 0; mf < 2; mf++)
            #pragma unroll
            for (int nf = 0; nf < 4; nf++)
                #pragma unroll
                for (int q = 0; q < 4; q++) acc[mf][nf][q] = 0.f;

        unsigned bB = smb + B_OFF + (t & 1) * 65536;
        #pragma unroll
        for (int ks = 0; ks < 16; ks++) {
            unsigned afr[2][4], bfr[8];
            #pragma unroll
            for (int mf = 0; mf < 2; mf++)
                ldsm4(afr[mf][0], afr[mf][1], afr[mf][2], afr[mf][3],
                      aBase[mf] + ((ks << 5) ^ xA[mf]));
            #pragma unroll
            for (int nfp = 0; nfp < 2; nfp++) {
                unsigned q0, q1, q2, q3;
                ldsm4(q0, q1, q2, q3, bB + bRow[nfp] + ((ks << 5) ^ xB[nfp]));
                bfr[nfp * 4 + 0] = q0; bfr[nfp * 4 + 1] = q2;   // nf even: {k0,k8}
                bfr[nfp * 4 + 2] = q1; bfr[nfp * 4 + 3] = q3;   // nf odd
            }
            #pragma unroll
            for (int mf = 0; mf < 2; mf++)
                #pragma unroll
                for (int nf = 0; nf < 4; nf++)
                    mma16816(acc[mf][nf], afr[mf], bfr[nf * 2], bfr[nf * 2 + 1]);
        }

        // epilogue: s = se - 2*dot, store half2
        #pragma unroll
        for (int mf = 0; mf < 2; mf++) {
            int gr0 = row0 + wm * 32 + mf * 16 + (l >> 2);
            #pragma unroll
            for (int nf = 0; nf < 4; nf++) {
                int gc = t * 128 + wn * 32 + nf * 8 + (l & 3) * 2;
                float se0 = se_sm[gc], se1 = se_sm[gc + 1];
                float s00 = fmaf(-2.f, acc[mf][nf][0], se0);
                float s01 = fmaf(-2.f, acc[mf][nf][1], se1);
                float s10 = fmaf(-2.f, acc[mf][nf][2], se0);
                float s11 = fmaf(-2.f, acc[mf][nf][3], se1);
                *(__half2*)(g_t + (size_t)gr0 * NE + gc)       = __floats2half2_rn(s00, s01);
                *(__half2*)(g_t + (size_t)(gr0 + 8) * NE + gc) = __floats2half2_rn(s10, s11);
            }
        }
        __syncthreads();
    }
}

// ================= exact rescore of shortlist =================
__global__ void __launch_bounds__(256) rescore_kernel(const float* __restrict__ emb,
                                                      float* __restrict__ out) {
    __shared__ int    s_cand[8][256];
    __shared__ int    s_cnt[8];
    __shared__ double s_wd[8];
    int w = threadIdx.x >> 5, lane = threadIdx.x & 31;
    int row = blockIdx.x * 8 + w;
    if (lane == 0) s_cnt[w] = 0;

    const uint2* tp = (const uint2*)(g_t + (size_t)row * NE);
    uint2 u[8];
    float f[8][4];
    float mn = CUDART_INF_F;
    #pragma unroll
    for (int q = 0; q < 8; q++) {
        u[q] = tp[q * 32 + lane];
        __half2 h0 = *(__half2*)&u[q].x, h1 = *(__half2*)&u[q].y;
        f[q][0] = __low2float(h0); f[q][1] = __high2float(h0);
        f[q][2] = __low2float(h1); f[q][3] = __high2float(h1);
        mn = fminf(mn, fminf(fminf(f[q][0], f[q][1]), fminf(f[q][2], f[q][3])));
    }
    #pragma unroll
    for (int off = 16; off; off >>= 1)
        mn = fminf(mn, __shfl_xor_sync(0xffffffffu, mn, off));
    float thr = mn + MARGIN;
    __syncwarp();

    #pragma unroll
    for (int q = 0; q < 8; q++) {
        int cbase = (q * 32 + lane) * 4;
        #pragma unroll
        for (int e = 0; e < 4; e++)
            if (f[q][e] <= thr) {
                int p = atomicAdd(&s_cnt[w], 1);
                if (p < 256) s_cand[w][p] = cbase + e;
            }
    }
    __syncwarp();
    int cnt = min(s_cnt[w], 256);

    float bd = CUDART_INF_F; int bj = 0x7fffffff;
    float szr = g_sz[row];
    const float* zp = g_zrm + (size_t)row * CDIM;
    for (int i = lane; i < cnt; i += 32) {
        int j = s_cand[w][i];
        const float* ep = emb + (size_t)j * CDIM;
        float acc = 0.f;
        #pragma unroll 8
        for (int k = 0; k < 256; k++) acc = fmaf(zp[k], ep[k], acc);   // exact R1 order
        float d = fmaf(-2.f, acc, __fadd_rn(szr, g_se[j]));            // exact R1 rounding
        if (d < bd || (d == bd && j < bj)) { bd = d; bj = j; }
    }
    #pragma unroll
    for (int off = 16; off; off >>= 1) {
        float od = __shfl_down_sync(0xffffffffu, bd, off);
        int   oj = __shfl_down_sync(0xffffffffu, bj, off);
        if (od < bd || (od == bd && oj < bj)) { bd = od; bj = oj; }
    }
    if (lane == 0) { out[row] = (float)bj; s_wd[w] = (double)bd; }
    __syncthreads();
    if (threadIdx.x == 0) {
        double p = 0.0;
        #pragma unroll
        for (int i = 0; i < 8; i++) p += s_wd[i];
        g_partial[blockIdx.x] = p;
    }
}

// ================= loss finalize =================
__global__ void loss2_kernel(float* __restrict__ out, int out_size) {
    __shared__ double s[1024];
    int t = threadIdx.x;
    s[t] = g_partial[t] + g_partial[t + 1024] + g_partial[t + 2048] + g_partial[t + 3072];
    __syncthreads();
    for (int off = 512; off; off >>= 1) {
        if (t < off) s[t] += s[t + off];
        __syncthreads();
    }
    if (t == 0 && out_size > NROW) {
        float m = (float)(s[0] / (double)((size_t)NROW * CDIM));
        out[NROW] = m + 0.25f * m;
    }
}

extern "C" void kernel_launch(void* const* d_in, const int* in_sizes, int n_in,
                              void* d_out, int out_size) {
    const float* z   = (const float*)d_in[0];   // (32,256,32,32) fp32
    const float* emb = (const float*)d_in[1];   // (1024,256)     fp32
    float* out = (float*)d_out;

    zprep_kernel<<<dim3(32, 8, 32), dim3(32, 8)>>>(z);
    eprep_kernel<<<1024, 256>>>(emb);
    se_kernel<<<1024, 64>>>(emb);
    sz2_kernel<<<1024, 256>>>();

    static int smem_set = 0;
    if (!smem_set) {
        cudaFuncSetAttribute(gemm_kernel, cudaFuncAttributeMaxDynamicSharedMemorySize, SMEM_T);
        smem_set = 1;
    }
    gemm_kernel<<<256, 512, SMEM_T>>>();

    rescore_kernel<<<4096, 256>>>(emb, out);
    loss2_kernel<<<1, 1024>>>(out, out_size);
}